// round 7
// baseline (speedup 1.0000x reference)
#include <cuda_runtime.h>
#include <math.h>

#define NC    10
#define NG    8
#define TPB   256
#define WPB   (TPB / 32)
#define POOLQ 256                 // int4 labels per count/place block
#define MAXB  2048
#define MAXN  500000
#define B2    59                  // blocks per class in k_gather
#define GRID2 (NC * B2)           // 590 ~= one full wave (4 blocks/SM * 148)

// Scratch (__device__ globals; zero-init at load; finalize resets accumulators)
__device__ int      g_idx[NC][MAXN];     // per-class SORTED row-index lists
__device__ int      g_bcnt[MAXB][NC];    // per-block class histograms
__device__ int      g_boff[MAXB][NC];    // exclusive offsets per block/class
__device__ int      g_cnt[NC];           // class totals (assigned, not accumulated)
__device__ float    g_S[NC * NG];
__device__ float    g_V[NC * NG];
__device__ unsigned g_ticket;

// ---------------------------------------------------------------------------
// k_count: per-block per-class histograms (one int4 label load per thread).
__global__ __launch_bounds__(TPB) void k_count(const int* __restrict__ labels,
                                               int N, int nq, int nb) {
    __shared__ int s_cnt[NC];
    if (threadIdx.x < NC) s_cnt[threadIdx.x] = 0;
    __syncthreads();

    const int lane = threadIdx.x & 31;
    const int4* lab4 = (const int4*)labels;
    int q = blockIdx.x * POOLQ + threadIdx.x;
    int4 lb = make_int4(0, 0, 0, 0);
    if (q < nq) lb = lab4[q];

    #define CNT1(CC) {                                                          \
        int cc_ = (CC);                                                         \
        unsigned m = __match_any_sync(0xFFFFFFFFu, cc_);                        \
        if ((unsigned)cc_ < NC && lane == __ffs(m) - 1)                         \
            atomicAdd(&s_cnt[cc_], __popc(m)); }
    CNT1(lb.x - 1) CNT1(lb.y - 1) CNT1(lb.z - 1) CNT1(lb.w - 1)
    // scalar tail (N % 4) counted by last block (warp-uniform loop bound)
    if (blockIdx.x == nb - 1) {
        for (int nbase = nq << 2; nbase < N; nbase += TPB) {
            int n = nbase + threadIdx.x;
            int lv = (n < N) ? labels[n] : 0;
            CNT1(lv - 1)
        }
    }
    #undef CNT1
    __syncthreads();
    if (threadIdx.x < NC) g_bcnt[blockIdx.x][threadIdx.x] = s_cnt[threadIdx.x];
}

// ---------------------------------------------------------------------------
// k_scan: one warp per class scans nb block-counts -> exclusive offsets + total.
__global__ void k_scan(int nb) {
    const int c    = threadIdx.x >> 5;      // launched with NC*32 threads
    const int lane = threadIdx.x & 31;
    int carry = 0;
    for (int base = 0; base < nb; base += 32) {
        int b = base + lane;
        int val = (b < nb) ? g_bcnt[b][c] : 0;
        int incl = val;
        #pragma unroll
        for (int o = 1; o < 32; o <<= 1) {
            int t = __shfl_up_sync(0xFFFFFFFFu, incl, o);
            if (lane >= o) incl += t;
        }
        if (b < nb) g_boff[b][c] = carry + incl - val;
        carry += __shfl_sync(0xFFFFFFFFu, incl, 31);
    }
    if (lane == 0) g_cnt[c] = carry;
}

// ---------------------------------------------------------------------------
// k_place: write each matched row index to its exact sorted global slot.
// Warp w owns labels [q0+w*32 .. q0+w*32+31] (int4) — per-warp class counts,
// block-local scan over warps, then ballot-ranked placement (sorted output).
__global__ __launch_bounds__(TPB) void k_place(const int* __restrict__ labels,
                                               int N, int nq, int nb) {
    __shared__ int wcnt[WPB][NC];
    __shared__ int wcur[WPB][NC];
    __shared__ int s_boff[NC];
    const int w    = threadIdx.x >> 5;
    const int lane = threadIdx.x & 31;
    const unsigned ltmask = (1u << lane) - 1u;

    if (lane < NC) wcnt[w][lane] = 0;
    __syncthreads();

    const int4* lab4 = (const int4*)labels;
    int q = blockIdx.x * POOLQ + threadIdx.x;
    int4 lb = make_int4(0, 0, 0, 0);
    if (q < nq) lb = lab4[q];
    const bool tailW = (blockIdx.x == nb - 1) && (w == WPB - 1) && ((N & 3) != 0);

    // phase 1: per-warp counts
    #define CNTW(CC) {                                                          \
        int cc_ = (CC);                                                         \
        unsigned m = __match_any_sync(0xFFFFFFFFu, cc_);                        \
        if ((unsigned)cc_ < NC && lane == __ffs(m) - 1)                         \
            atomicAdd(&wcnt[w][cc_], __popc(m)); }
    CNTW(lb.x - 1) CNTW(lb.y - 1) CNTW(lb.z - 1) CNTW(lb.w - 1)
    if (tailW) {
        for (int nbase = nq << 2; nbase < N; nbase += 32) {
            int n = nbase + lane;
            int lv = (n < N) ? labels[n] : 0;
            CNTW(lv - 1)
        }
    }
    #undef CNTW
    __syncthreads();

    // block-local exclusive scan over warps; load global base offsets
    if (threadIdx.x < NC) {
        int acc = 0;
        #pragma unroll
        for (int ww = 0; ww < WPB; ++ww) {
            int t = wcnt[ww][threadIdx.x];
            wcur[ww][threadIdx.x] = acc;
            acc += t;
        }
        s_boff[threadIdx.x] = g_boff[blockIdx.x][threadIdx.x];
    }
    __syncthreads();

    // phase 2: place (shared cursor per warp/class preserves program order)
    #define PUT(CC, NN) {                                                       \
        int cc_ = (CC);                                                         \
        unsigned m = __match_any_sync(0xFFFFFFFFu, cc_);                        \
        int ldr = __ffs(m) - 1;                                                 \
        int bpos = 0;                                                           \
        if ((unsigned)cc_ < NC && lane == ldr)                                  \
            bpos = atomicAdd(&wcur[w][cc_], __popc(m));                         \
        bpos = __shfl_sync(0xFFFFFFFFu, bpos, ldr);                             \
        if ((unsigned)cc_ < NC)                                                 \
            g_idx[cc_][s_boff[cc_] + bpos + __popc(m & ltmask)] = (NN); }
    {
        int n = q << 2;
        PUT(lb.x - 1, n) PUT(lb.y - 1, n + 1) PUT(lb.z - 1, n + 2) PUT(lb.w - 1, n + 3)
    }
    if (tailW) {
        for (int nbase = nq << 2; nbase < N; nbase += 32) {
            int n = nbase + lane;
            int lv = (n < N) ? labels[n] : 0;
            PUT(lv - 1, n)
        }
    }
    #undef PUT
}

// ---------------------------------------------------------------------------
// Per-row accumulate: S_i += a_i;  V_i += a_i * (R - log a_i), R = sum log a_j
#define ACC(AQ, BQ)                                                             \
    {                                                                           \
        float a[NG] = {(AQ).x, (AQ).y, (AQ).z, (AQ).w,                          \
                       (BQ).x, (BQ).y, (BQ).z, (BQ).w};                         \
        float la[NG]; float R = 0.0f;                                           \
        _Pragma("unroll")                                                       \
        for (int g = 0; g < NG; ++g) { la[g] = __logf(a[g]); R += la[g]; }      \
        _Pragma("unroll")                                                       \
        for (int g = 0; g < NG; ++g) {                                          \
            s[g] += a[g];                                                       \
            v[g] = fmaf(a[g], R - la[g], v[g]);                                 \
        }                                                                       \
    }
// Weighted variant for the predicated tail batch (wk in {0,1})
#define WACC(AQ, BQ, WK)                                                        \
    {                                                                           \
        float a[NG] = {(AQ).x, (AQ).y, (AQ).z, (AQ).w,                          \
                       (BQ).x, (BQ).y, (BQ).z, (BQ).w};                         \
        float la[NG]; float R = 0.0f;                                           \
        _Pragma("unroll")                                                       \
        for (int g = 0; g < NG; ++g) { la[g] = __logf(a[g]); R += la[g]; }      \
        _Pragma("unroll")                                                       \
        for (int g = 0; g < NG; ++g) {                                          \
            s[g] = fmaf((WK), a[g], s[g]);                                      \
            v[g] = fmaf((WK) * a[g], R - la[g], v[g]);                          \
        }                                                                       \
    }

// ---------------------------------------------------------------------------
// k_gather: each block sweeps a CONTIGUOUS chunk of a sorted per-class list
// (ascending addresses). Batched 4-deep loads; last-block ticket finalize.
__global__ __launch_bounds__(TPB) void k_gather(const float* __restrict__ act,
                                                int N, float* __restrict__ out) {
    const int cc = blockIdx.x / B2;
    const int b  = blockIdx.x % B2;
    const size_t clsBase = (size_t)cc * (size_t)N;
    const int cnt = __ldcg(&g_cnt[cc]);
    const int* __restrict__ lst = g_idx[cc];
    const int lo = (int)(((long long)cnt * b) / B2);
    const int hi = (int)(((long long)cnt * (b + 1)) / B2);

    float s[NG] = {0,0,0,0,0,0,0,0};
    float v[NG] = {0,0,0,0,0,0,0,0};

    int i = lo + threadIdx.x;
    // full 4-batches
    while (i + 3 * TPB < hi) {
        int n0 = __ldg(lst + i);
        int n1 = __ldg(lst + i + TPB);
        int n2 = __ldg(lst + i + 2 * TPB);
        int n3 = __ldg(lst + i + 3 * TPB);
        const float4* p0 = (const float4*)(act + (clsBase + (size_t)n0) * NG);
        const float4* p1 = (const float4*)(act + (clsBase + (size_t)n1) * NG);
        const float4* p2 = (const float4*)(act + (clsBase + (size_t)n2) * NG);
        const float4* p3 = (const float4*)(act + (clsBase + (size_t)n3) * NG);
        float4 x0 = p0[0], y0 = p0[1];
        float4 x1 = p1[0], y1 = p1[1];
        float4 x2 = p2[0], y2 = p2[1];
        float4 x3 = p3[0], y3 = p3[1];
        ACC(x0, y0) ACC(x1, y1) ACC(x2, y2) ACC(x3, y3)
        i += 4 * TPB;
    }
    // predicated final batch (covers up to 4 remaining strides)
    if (i < hi) {
        int i1 = i + TPB, i2 = i + 2 * TPB, i3 = i + 3 * TPB;
        float w1 = (i1 < hi) ? 1.0f : 0.0f;
        float w2 = (i2 < hi) ? 1.0f : 0.0f;
        float w3 = (i3 < hi) ? 1.0f : 0.0f;
        int n0 = __ldg(lst + i);
        int n1 = (i1 < hi) ? __ldg(lst + i1) : n0;
        int n2 = (i2 < hi) ? __ldg(lst + i2) : n0;
        int n3 = (i3 < hi) ? __ldg(lst + i3) : n0;
        const float4* p0 = (const float4*)(act + (clsBase + (size_t)n0) * NG);
        const float4* p1 = (const float4*)(act + (clsBase + (size_t)n1) * NG);
        const float4* p2 = (const float4*)(act + (clsBase + (size_t)n2) * NG);
        const float4* p3 = (const float4*)(act + (clsBase + (size_t)n3) * NG);
        float4 x0 = p0[0], y0 = p0[1];
        float4 x1 = p1[0], y1 = p1[1];
        float4 x2 = p2[0], y2 = p2[1];
        float4 x3 = p3[0], y3 = p3[1];
        ACC(x0, y0)
        WACC(x1, y1, w1) WACC(x2, y2, w2) WACC(x3, y3, w3)
    }

    // warp tree-reduce 16 values (all threads converged here)
    #pragma unroll
    for (int o = 16; o > 0; o >>= 1) {
        #pragma unroll
        for (int g = 0; g < NG; ++g) {
            s[g] += __shfl_down_sync(0xFFFFFFFFu, s[g], o);
            v[g] += __shfl_down_sync(0xFFFFFFFFu, v[g], o);
        }
    }

    __shared__ float sh[2 * NG];
    __shared__ bool amLast;
    __shared__ float pc[NC];
    if (threadIdx.x < 2 * NG) sh[threadIdx.x] = 0.0f;
    __syncthreads();
    if ((threadIdx.x & 31) == 0) {
        #pragma unroll
        for (int g = 0; g < NG; ++g) {
            atomicAdd(&sh[g], s[g]);
            atomicAdd(&sh[NG + g], v[g]);
        }
    }
    __syncthreads();
    if (threadIdx.x < NG) {
        atomicAdd(&g_S[cc * NG + threadIdx.x], sh[threadIdx.x]);
        atomicAdd(&g_V[cc * NG + threadIdx.x], sh[NG + threadIdx.x]);
    }

    // ---- last-block finalize ----
    __threadfence();
    if (threadIdx.x == 0)
        amLast = (atomicAdd(&g_ticket, 1u) == (unsigned)(GRID2 - 1));
    __syncthreads();
    if (!amLast) return;

    int t = threadIdx.x;
    if (t < NC) pc[t] = 0.0f;
    __syncthreads();
    if (t < NC * NG) {
        float S = __ldcg(&g_S[t]);
        float V = __ldcg(&g_V[t]);
        float term = V / S - (float)(NG - 1) * logf(S);
        atomicAdd(&pc[t / NG], term);
    }
    __syncthreads();
    if (t == 0) {
        float num = 0.0f, vcnt = 0.0f;
        #pragma unroll
        for (int c = 0; c < NC; ++c) {
            int cn = __ldcg(&g_cnt[c]);
            if (cn >= 2) { num += pc[c]; vcnt += 1.0f; }
        }
        out[0] = num / (vcnt * (float)(NG * (NG - 1)));
        g_ticket = 0;                         // reset for next replay
    }
    __syncthreads();
    if (t < NC * NG) { g_S[t] = 0.0f; g_V[t] = 0.0f; }
    // g_cnt/g_bcnt/g_boff/g_idx are fully overwritten each run; no reset needed
}

// ---------------------------------------------------------------------------
extern "C" void kernel_launch(void* const* d_in, const int* in_sizes, int n_in,
                              void* d_out, int out_size) {
    const float* act  = (const float*)d_in[0];   // [C, N, G] float32
    const int* labels = (const int*)d_in[1];     // [N] int32
    const int N = in_sizes[1];

    const int nq = N >> 2;
    int nb = (nq + POOLQ - 1) / POOLQ;
    if (nb < 1) nb = 1;

    k_count<<<nb, TPB>>>(labels, N, nq, nb);
    k_scan<<<1, NC * 32>>>(nb);
    k_place<<<nb, TPB>>>(labels, N, nq, nb);
    k_gather<<<GRID2, TPB>>>(act, N, (float*)d_out);
}

// round 9
// speedup vs baseline: 1.2545x; 1.2545x over previous
#include <cuda_runtime.h>
#include <math.h>

#define NC    10
#define NG    8
#define TPB   256
#define WPB   (TPB / 32)
#define MAXE  131072              // per-class entry capacity (>= 125001)
#define B2    59
#define GRID2 (NC * B2)

// Scratch (__device__ globals; zero-init at load; finalize resets for replays)
__device__ int      g_lst[NC][MAXE];   // per-class (line<<4 | mask) entries
__device__ int      g_cur[NC];         // per-class entry counts
__device__ int      g_rowcnt[NC];      // per-class matched-row counts
__device__ float    g_S[NC * NG];
__device__ float    g_V[NC * NG];
__device__ unsigned g_ticket;

// ---------------------------------------------------------------------------
// k_bucket: one label pass. Each thread owns one quad (= one 128B line of every
// class plane); emits (line<<4|mask) entries for each distinct matched class.
// Shared staging grouped by class, one global reserve per class per block.
__global__ __launch_bounds__(TPB) void k_bucket(const int* __restrict__ labels,
                                                int N, int nq) {
    __shared__ int s_cnt[NC], s_off[NC], s_place[NC], s_gbase[NC], s_rcnt[NC];
    __shared__ int s_pool[TPB * 4];

    const int tid = threadIdx.x;
    if (tid < NC) { s_cnt[tid] = 0; s_place[tid] = 0; s_rcnt[tid] = 0; }
    __syncthreads();

    const int q = blockIdx.x * TPB + tid;
    int4 lb = make_int4(0, 0, 0, 0);
    if ((q << 2) < N) {
        if (q < nq) lb = ((const int4*)labels)[q];
        else {                               // partial final quad (N % 4 != 0)
            int base = q << 2;
            lb.x = labels[base];
            lb.y = (base + 1 < N) ? labels[base + 1] : 0;
            lb.z = (base + 2 < N) ? labels[base + 2] : 0;
            lb.w = (base + 3 < N) ? labels[base + 3] : 0;
        }
    }
    int cs[4] = {lb.x - 1, lb.y - 1, lb.z - 1, lb.w - 1};
    int ent_c[4], ent_m[4], ne = 0;
    #pragma unroll
    for (int i = 0; i < 4; ++i) {
        int c = cs[i];
        if ((unsigned)c < NC) {
            bool dup = false;
            #pragma unroll
            for (int j = 0; j < 4; ++j)
                if (j < i && cs[j] == c) dup = true;
            if (!dup) {
                int m = 0;
                #pragma unroll
                for (int j = 0; j < 4; ++j)
                    if (j >= i && cs[j] == c) m |= 1 << j;
                ent_c[ne] = c; ent_m[ne] = m; ne++;
                atomicAdd(&s_cnt[c], 1);
                atomicAdd(&s_rcnt[c], __popc(m));
            }
        }
    }
    __syncthreads();
    if (tid == 0) {
        int acc = 0;
        #pragma unroll
        for (int c = 0; c < NC; ++c) { s_off[c] = acc; acc += s_cnt[c]; }
    }
    __syncthreads();
    if (tid < NC) {
        s_gbase[tid] = atomicAdd(&g_cur[tid], s_cnt[tid]);
        atomicAdd(&g_rowcnt[tid], s_rcnt[tid]);
    }
    for (int e = 0; e < ne; ++e) {
        int c = ent_c[e];
        int p = atomicAdd(&s_place[c], 1);
        s_pool[s_off[c] + p] = (q << 4) | ent_m[e];
    }
    __syncthreads();
    for (int c = 0; c < NC; ++c) {
        int cnt = s_cnt[c], gb = s_gbase[c], so = s_off[c];
        for (int i = tid; i < cnt; i += TPB)
            g_lst[c][gb + i] = s_pool[so + i];
    }
}

// ---------------------------------------------------------------------------
// k_gline: warp-cooperative line gather. 8 lanes per line: lane (g=l>>3, k=l&7)
// loads float4 #k of line #g of the 4-entry batch -> one fully-coalesced
// LDG.128 per batch covering 4 x 128B lines. Row r=k>>1, half h=k&1. Each lane
// keeps 4-wide accumulators for g-cols [4h,4h+4); lane pair (l, l^1) exchanges
// half-row log-sums. Unroll 4 batches (16 entries) for MLP.
// NaN guard: unmatched rows are replaced by (1,1,1,1) BEFORE the log — their
// elements may contain exact 0.0 (never logged by the reference), and
// 0 * (R - (-inf)) = NaN would otherwise poison the accumulators.
__global__ __launch_bounds__(TPB) void k_gline(const float* __restrict__ act,
                                               int N, float* __restrict__ out) {
    const int cc   = blockIdx.x / B2;
    const int b    = blockIdx.x % B2;
    const int w    = threadIdx.x >> 5;
    const int lane = threadIdx.x & 31;
    const int g    = lane >> 3;
    const int k    = lane & 7;
    const int r    = k >> 1;
    const int h    = k & 1;
    const size_t rowScale = (size_t)NG;
    const size_t clsRows  = (size_t)cc * (size_t)N;

    const int cnt = __ldcg(&g_cur[cc]);
    const int* __restrict__ lst = g_lst[cc];
    const int lo = (int)(((long long)cnt * b) / B2);
    const int hi = (int)(((long long)cnt * (b + 1)) / B2);

    float s4[4] = {0, 0, 0, 0};
    float v4[4] = {0, 0, 0, 0};

    for (int base = lo + w * 16; base < hi; base += WPB * 16) {
        float4 a[4]; float wg[4];
        #pragma unroll
        for (int u = 0; u < 4; ++u) {
            int ei = base + u * 4 + g;
            int e  = (ei < hi) ? __ldg(lst + ei) : 0;   // dummy: line 0, mask 0
            int L  = e >> 4;
            int m  = e & 15;
            wg[u]  = (float)((m >> r) & 1);
            int rowN = (L << 2) + r;
            a[u] = make_float4(1.0f, 1.0f, 1.0f, 1.0f);
            if (rowN < N && m != 0)
                a[u] = *(const float4*)(act + (clsRows + (size_t)rowN) * rowScale
                                        + ((size_t)h << 2));
            if (wg[u] == 0.0f) a[u] = make_float4(1.0f, 1.0f, 1.0f, 1.0f);
        }
        #pragma unroll
        for (int u = 0; u < 4; ++u) {
            float av[4] = {a[u].x, a[u].y, a[u].z, a[u].w};
            float la[4]; float Rh = 0.0f;
            #pragma unroll
            for (int j = 0; j < 4; ++j) { la[j] = __logf(av[j]); Rh += la[j]; }
            float R = Rh + __shfl_xor_sync(0xFFFFFFFFu, Rh, 1);
            #pragma unroll
            for (int j = 0; j < 4; ++j) {
                float wa = wg[u] * av[j];
                s4[j] += wa;
                v4[j] = fmaf(wa, R - la[j], v4[j]);
            }
        }
    }

    // parity-preserving warp reduce (even offsets: lane0 <- h=0, lane1 <- h=1)
    #pragma unroll
    for (int o = 16; o >= 2; o >>= 1) {
        #pragma unroll
        for (int j = 0; j < 4; ++j) {
            s4[j] += __shfl_down_sync(0xFFFFFFFFu, s4[j], o);
            v4[j] += __shfl_down_sync(0xFFFFFFFFu, v4[j], o);
        }
    }

    __shared__ float sh[2 * NG];
    __shared__ bool amLast;
    __shared__ float pc[NC];
    if (threadIdx.x < 2 * NG) sh[threadIdx.x] = 0.0f;
    __syncthreads();
    if (lane < 2) {                      // lane0: cols 0-3, lane1: cols 4-7
        #pragma unroll
        for (int j = 0; j < 4; ++j) {
            atomicAdd(&sh[lane * 4 + j],      s4[j]);
            atomicAdd(&sh[NG + lane * 4 + j], v4[j]);
        }
    }
    __syncthreads();
    if (threadIdx.x < NG) {
        atomicAdd(&g_S[cc * NG + threadIdx.x], sh[threadIdx.x]);
        atomicAdd(&g_V[cc * NG + threadIdx.x], sh[NG + threadIdx.x]);
    }

    // ---- last-block finalize ----
    __threadfence();
    if (threadIdx.x == 0)
        amLast = (atomicAdd(&g_ticket, 1u) == (unsigned)(GRID2 - 1));
    __syncthreads();
    if (!amLast) return;

    int t = threadIdx.x;
    if (t < NC) pc[t] = 0.0f;
    __syncthreads();
    if (t < NC * NG) {
        float S = __ldcg(&g_S[t]);
        float V = __ldcg(&g_V[t]);
        float term = V / S - (float)(NG - 1) * logf(S);
        atomicAdd(&pc[t / NG], term);
    }
    __syncthreads();
    if (t == 0) {
        float num = 0.0f, vcnt = 0.0f;
        #pragma unroll
        for (int c = 0; c < NC; ++c) {
            int cn = __ldcg(&g_rowcnt[c]);
            if (cn >= 2) { num += pc[c]; vcnt += 1.0f; }
        }
        out[0] = num / (vcnt * (float)(NG * (NG - 1)));
        g_ticket = 0;
    }
    __syncthreads();
    if (t < NC * NG) { g_S[t] = 0.0f; g_V[t] = 0.0f; }
    if (t < NC) { g_cur[t] = 0; g_rowcnt[t] = 0; }
}

// ---------------------------------------------------------------------------
extern "C" void kernel_launch(void* const* d_in, const int* in_sizes, int n_in,
                              void* d_out, int out_size) {
    const float* act  = (const float*)d_in[0];   // [C, N, G] float32
    const int* labels = (const int*)d_in[1];     // [N] int32
    const int N = in_sizes[1];

    const int nq     = N >> 2;                   // full quads
    const int nlines = (N + 3) >> 2;             // lines incl. partial
    int nb = (nlines + TPB - 1) / TPB;
    if (nb < 1) nb = 1;

    k_bucket<<<nb, TPB>>>(labels, N, nq);
    k_gline<<<GRID2, TPB>>>(act, N, (float*)d_out);
}

// round 10
// speedup vs baseline: 1.7273x; 1.3769x over previous
#include <cuda_runtime.h>
#include <math.h>

#define NC 10
#define NG 8
#define TPB 256
#define WARPS (TPB / 32)
#define QCAP 256           // ring capacity per warp (power of 2)
#define BPC 60             // blocks per class
#define GRID (NC * BPC)

// Scratch (__device__ globals; zero-init at load; finalize resets for replays)
__device__ float g_S[NC * NG];
__device__ float g_V[NC * NG];
__device__ float g_count[NC];
__device__ unsigned g_ticket;

// Per-row accumulate: S_i += a_i;  V_i += a_i * (R - log a_i), R = sum log a_j
#define ACC(AQ, BQ)                                                             \
    {                                                                           \
        float a[NG] = {(AQ).x, (AQ).y, (AQ).z, (AQ).w,                          \
                       (BQ).x, (BQ).y, (BQ).z, (BQ).w};                         \
        float la[NG]; float R = 0.0f;                                           \
        _Pragma("unroll")                                                       \
        for (int g = 0; g < NG; ++g) { la[g] = __logf(a[g]); R += la[g]; }      \
        _Pragma("unroll")                                                       \
        for (int g = 0; g < NG; ++g) {                                          \
            s[g] += a[g];                                                       \
            v[g] = fmaf(a[g], R - la[g], v[g]);                                 \
        }                                                                       \
    }

// ---------------------------------------------------------------------------
// Single fused kernel: warp-compacted class scan + DEEP-BATCHED gather +
// last-block finalize. Each block owns ONE class. Warps scan labels (int4,
// warp-uniform bounds), ballot-compact matched row indices into a shared ring,
// and drain in 128-row batches: each thread hoists 4 rows (8 independent
// LDG.128) before computing, exposing ~4x the memory-level parallelism of the
// one-row-per-thread drain.
__global__ __launch_bounds__(TPB, 4) void k_all(const float* __restrict__ act,
                                                const int* __restrict__ labels,
                                                int N, float* __restrict__ out) {
    const int c    = blockIdx.x / BPC;
    const int b    = blockIdx.x % BPC;
    const int w    = threadIdx.x >> 5;
    const int lane = threadIdx.x & 31;
    const int want = c + 1;
    const size_t clsBase = (size_t)c * (size_t)N;

    __shared__ int qbuf[WARPS][QCAP];
    __shared__ float sh[2 * NG + 1];
    __shared__ bool amLast;
    __shared__ float pc[NC];

    if (threadIdx.x < 2 * NG + 1) sh[threadIdx.x] = 0.0f;
    __syncthreads();

    float s[NG] = {0,0,0,0,0,0,0,0};
    float v[NG] = {0,0,0,0,0,0,0,0};

    unsigned head = 0, tail = 0;   // warp-uniform ring cursors

    const int nq = N >> 2;
    const int4* lab4 = (const int4*)labels;
    const int gw     = b * WARPS + w;
    const int stride = BPC * WARPS * 32;
    const unsigned ltmask = (1u << lane) - 1u;

    // 4-deep batch: 128 queued rows, 4 rows per thread, loads hoisted.
    #define BATCH128()                                                          \
        {                                                                       \
            __syncwarp();                                                       \
            int i0 = qbuf[w][(head + lane)      & (QCAP - 1)];                  \
            int i1 = qbuf[w][(head + lane + 32) & (QCAP - 1)];                  \
            int i2 = qbuf[w][(head + lane + 64) & (QCAP - 1)];                  \
            int i3 = qbuf[w][(head + lane + 96) & (QCAP - 1)];                  \
            head += 128;                                                        \
            const float4* p0 = (const float4*)(act + (clsBase + (size_t)i0) * NG); \
            const float4* p1 = (const float4*)(act + (clsBase + (size_t)i1) * NG); \
            const float4* p2 = (const float4*)(act + (clsBase + (size_t)i2) * NG); \
            const float4* p3 = (const float4*)(act + (clsBase + (size_t)i3) * NG); \
            float4 x0 = p0[0], y0 = p0[1];                                      \
            float4 x1 = p1[0], y1 = p1[1];                                      \
            float4 x2 = p2[0], y2 = p2[1];                                      \
            float4 x3 = p3[0], y3 = p3[1];                                      \
            ACC(x0, y0) ACC(x1, y1) ACC(x2, y2) ACC(x3, y3)                     \
        }

    #define BATCH32()                                                           \
        {                                                                       \
            __syncwarp();                                                       \
            int idx = qbuf[w][(head + lane) & (QCAP - 1)];                      \
            head += 32;                                                         \
            const float4* r = (const float4*)(act + (clsBase + (size_t)idx) * NG); \
            float4 aq = r[0], bq = r[1];                                        \
            ACC(aq, bq)                                                         \
        }

    #define SLOT(LV, OFF)                                                      \
        {                                                                       \
            unsigned m = __ballot_sync(0xFFFFFFFFu, (LV) == want);              \
            if ((LV) == want)                                                   \
                qbuf[w][(tail + __popc(m & ltmask)) & (QCAP - 1)] = n + (OFF);  \
            tail += __popc(m);                                                  \
        }

    // Warp-uniform outer loop: 'base' is identical across the warp.
    for (int base = gw * 32; base < nq; base += stride) {
        int q = base + lane;
        int4 lb;
        if (q < nq) lb = lab4[q];
        else        { lb.x = 0; lb.y = 0; lb.z = 0; lb.w = 0; }
        int n = q << 2;
        SLOT(lb.x, 0) SLOT(lb.y, 1) SLOT(lb.z, 2) SLOT(lb.w, 3)
        // max enqueued since last check: 128 -> worst case 255 in ring (<= QCAP)
        while (tail - head >= 128) BATCH128()
    }

    // Scalar tail of labels (N % 4): warp 0 of block 0 per class, uniform loop.
    if (b == 0 && w == 0) {
        int tstart = nq << 2;
        for (int nb = tstart; nb < N; nb += 32) {
            int n = nb + lane;
            int lv = (n < N) ? labels[n] : 0;
            unsigned m = __ballot_sync(0xFFFFFFFFu, lv == want);
            if (lv == want)
                qbuf[w][(tail + __popc(m & ltmask)) & (QCAP - 1)] = n;
            tail += __popc(m);
            while (tail - head >= 128) BATCH128()
        }
    }

    // Drain 32-row batches, then the final <32 with predication.
    while (tail - head >= 32) BATCH32()
    {
        unsigned rem = tail - head;
        __syncwarp();
        int idx = (lane < (int)rem) ? qbuf[w][(head + lane) & (QCAP - 1)] : 0;
        if (lane < (int)rem) {
            const float4* r = (const float4*)(act + (clsBase + (size_t)idx) * NG);
            float4 aq = r[0], bq = r[1];
            ACC(aq, bq)
        }
    }
    #undef SLOT
    #undef BATCH32
    #undef BATCH128

    float cnt = (float)tail;   // warp-uniform: rows this warp enqueued

    // warp tree-reduce 16 values (all lanes alive here)
    #pragma unroll
    for (int o = 16; o > 0; o >>= 1) {
        #pragma unroll
        for (int g = 0; g < NG; ++g) {
            s[g] += __shfl_down_sync(0xFFFFFFFFu, s[g], o);
            v[g] += __shfl_down_sync(0xFFFFFFFFu, v[g], o);
        }
    }

    if (lane == 0) {
        #pragma unroll
        for (int g = 0; g < NG; ++g) {
            atomicAdd(&sh[g], s[g]);
            atomicAdd(&sh[NG + g], v[g]);
        }
        atomicAdd(&sh[2 * NG], cnt);
    }
    __syncthreads();
    if (threadIdx.x < NG) {
        atomicAdd(&g_S[c * NG + threadIdx.x], sh[threadIdx.x]);
        atomicAdd(&g_V[c * NG + threadIdx.x], sh[NG + threadIdx.x]);
    }
    if (threadIdx.x == 2 * NG) atomicAdd(&g_count[c], sh[2 * NG]);

    // ---- last-block finalize ----
    __threadfence();
    if (threadIdx.x == 0)
        amLast = (atomicAdd(&g_ticket, 1u) == (unsigned)(GRID - 1));
    __syncthreads();
    if (!amLast) return;

    int t = threadIdx.x;
    if (t < NC) pc[t] = 0.0f;
    __syncthreads();
    if (t < NC * NG) {
        float S = __ldcg(&g_S[t]);
        float V = __ldcg(&g_V[t]);
        float term = V / S - (float)(NG - 1) * logf(S);
        atomicAdd(&pc[t / NG], term);
    }
    __syncthreads();
    if (t == 0) {
        float num = 0.0f, vcnt = 0.0f;
        #pragma unroll
        for (int cc = 0; cc < NC; ++cc) {
            float cn = __ldcg(&g_count[cc]);
            if (cn >= 2.0f) { num += pc[cc]; vcnt += 1.0f; }
        }
        out[0] = num / (vcnt * (float)(NG * (NG - 1)));
        g_ticket = 0;                               // reset for next replay
    }
    __syncthreads();
    if (t < NC * NG) { g_S[t] = 0.0f; g_V[t] = 0.0f; }
    if (t < NC) g_count[t] = 0.0f;
}

// ---------------------------------------------------------------------------
extern "C" void kernel_launch(void* const* d_in, const int* in_sizes, int n_in,
                              void* d_out, int out_size) {
    const float* act  = (const float*)d_in[0];   // [C, N, G] float32
    const int* labels = (const int*)d_in[1];     // [N] int32
    const int N = in_sizes[1];

    k_all<<<GRID, TPB>>>(act, labels, N, (float*)d_out);
}